// round 6
// baseline (speedup 1.0000x reference)
#include <cuda_runtime.h>

#define N_NODES 200000
#define HIDDIM  256
#define HEADS   8
#define HD      32
#define NC      1000
#define TR      32     // rows per tile in k_main
#define NB      200    // hist/scatter blocks
#define CHUNK   (N_NODES / NB)   // 1000, exact
#define SPLIT   4      // parts per cluster in k_main

// ---------------- device scratch ----------------
__device__ float g_QK[HIDDIM * HEADS];       // [hpair][j] float2 pairs, scale folded in
__device__ float g_bq[HEADS];
__device__ int   g_bh[NB * NC];              // per-block cluster histograms -> bases
__device__ int   g_offsets[NC + 1];
__device__ int   g_sorted[N_NODES];
__device__ float g_T[SPLIT * NC * HEADS * HIDDIM];  // per-part partial sums
__device__ float g_z[SPLIT * NC * HEADS];
__device__ float g_outc[NC * HIDDIM];

// ---------------- helpers ----------------
__device__ __forceinline__ unsigned su32(const void* p) {
    return (unsigned)__cvta_generic_to_shared(p);
}
__device__ __forceinline__ void cpa16(void* dst, const void* src) {
    asm volatile("cp.async.cg.shared.global [%0], [%1], 16;"
                 :: "r"(su32(dst)), "l"(src));
}
__device__ __forceinline__ void cpa_commit() {
    asm volatile("cp.async.commit_group;");
}
template <int NN> __device__ __forceinline__ void cpa_wait() {
    asm volatile("cp.async.wait_group %0;" :: "n"(NN));
}
__device__ __forceinline__ float2 ffma2(float2 a, float2 b, float2 c) {
    float2 d;
    asm("{\n\t"
        ".reg .b64 A,B,C,D;\n\t"
        "mov.b64 A,{%2,%3};\n\t"
        "mov.b64 B,{%4,%5};\n\t"
        "mov.b64 C,{%6,%7};\n\t"
        "fma.rn.f32x2 D,A,B,C;\n\t"
        "mov.b64 {%0,%1},D;\n\t"
        "}"
        : "=f"(d.x), "=f"(d.y)
        : "f"(a.x), "f"(a.y), "f"(b.x), "f"(b.y), "f"(c.x), "f"(c.y));
    return d;
}

// ---------------- prep (blocks 0..7) + per-block histogram (blocks 8..) ----------
__global__ void k_prep_hist(const float* __restrict__ Wk, const float* __restrict__ bk,
                            const float* __restrict__ pq, const int* __restrict__ ca) {
    __shared__ int sh[NC];
    int tid = threadIdx.x;
    if (blockIdx.x < 8) {
        const float scale = 0.1767766952966369f;  // 32^-0.5
        int h = blockIdx.x;
        int j = tid;
        float s = 0.f;
        #pragma unroll 8
        for (int d = 0; d < HD; d++)
            s += Wk[(h * HD + d) * HIDDIM + j] * pq[h * HD + d];
        g_QK[(((h >> 1) * HIDDIM) + j) * 2 + (h & 1)] = s * scale;
        if (j == 0) {
            float b = 0.f;
            for (int d = 0; d < HD; d++) b += bk[h * HD + d] * pq[h * HD + d];
            g_bq[h] = b * scale;
        }
        return;
    }
    int b = blockIdx.x - 8;
    for (int i = tid; i < NC; i += 256) sh[i] = 0;
    __syncthreads();
    int n0 = b * CHUNK;
    for (int i = tid; i < CHUNK; i += 256)
        atomicAdd(&sh[ca[n0 + i]], 1);
    __syncthreads();
    for (int i = tid; i < NC; i += 256) g_bh[b * NC + i] = sh[i];
}

// ---------------- scan: cluster offsets + per-block bases ----------------
__global__ void k_scan2() {
    __shared__ int buf[1024];
    int t = threadIdx.x;
    int total = 0;
    if (t < NC) {
        int s = 0;
        for (int b = 0; b < NB; b++) {
            int v = g_bh[b * NC + t];
            g_bh[b * NC + t] = s;
            s += v;
        }
        total = s;
    }
    buf[t] = total;
    __syncthreads();
    for (int off = 1; off < 1024; off <<= 1) {
        int add = (t >= off) ? buf[t - off] : 0;
        __syncthreads();
        buf[t] += add;
        __syncthreads();
    }
    if (t < NC) {
        int excl = buf[t] - total;
        g_offsets[t] = excl;
        for (int b = 0; b < NB; b++) g_bh[b * NC + t] += excl;
    }
    if (t == 0) g_offsets[NC] = N_NODES;
}

// ---------------- scatter (shared-memory cursors only) ----------------
__global__ void k_scatter2(const int* __restrict__ ca) {
    __shared__ int cur[NC];
    int b = blockIdx.x, tid = threadIdx.x;
    for (int i = tid; i < NC; i += 256) cur[i] = g_bh[b * NC + i];
    __syncthreads();
    int n0 = b * CHUNK;
    for (int i = tid; i < CHUNK; i += 256) {
        int n = n0 + i;
        int c = ca[n];
        int p = atomicAdd(&cur[c], 1);
        g_sorted[p] = n;
    }
}

// ---------------- main (fused scores + exp + weighted accum, quarter-clusters) ------
// dyn smem (bytes): xs 2*TR*256*4=65536 | QKs 8192 | es 1024 | zsh 256 | bqs 64
#define SM_XS   0
#define SM_QK   65536
#define SM_ES   (SM_QK + 8192)
#define SM_ZSH  (SM_ES + 1024)
#define SM_BQ   (SM_ZSH + 256)
#define SMEM_MAIN (SM_BQ + 64)

__global__ void __launch_bounds__(256) k_main(const float* __restrict__ x) {
    extern __shared__ char smem[];
    float*  xs  = (float*)(smem + SM_XS);          // [2][TR][256]
    float2* QKs = (float2*)(smem + SM_QK);         // [4][256]  (head-pairs)
    float*  esf = (float*)(smem + SM_ES);          // [TR][8]
    float*  zsh = (float*)(smem + SM_ZSH);         // [8][8]
    float*  bqs = (float*)(smem + SM_BQ);

    int tid = threadIdx.x;
    int warp = tid >> 5, lane = tid & 31;

    int cidx = blockIdx.x >> 2, part = blockIdx.x & 3;
    int cbase = g_offsets[cidx];
    int ccnt  = g_offsets[cidx + 1] - cbase;
    int ql    = (ccnt + 3) >> 2;
    int start = part * ql;
    int cnt   = min(ql, ccnt - start);
    if (cnt < 0) cnt = 0;
    int base  = cbase + start;
    int ntiles = (cnt + TR - 1) / TR;

    for (int i = tid; i < HIDDIM * 4; i += 256)
        QKs[i] = ((const float2*)g_QK)[i];
    if (tid < 8) bqs[tid] = g_bq[tid];
    __syncthreads();

    // T accumulators: thread owns 4 cols (cg*4..+3), rows r == q (mod 4)
    int q  = tid >> 6;       // row class 0..3
    int cg = tid & 63;       // col group
    float2 T[8][2];
    #pragma unroll
    for (int h = 0; h < 8; h++) { T[h][0] = make_float2(0.f, 0.f); T[h][1] = T[h][0]; }

    int g8 = lane >> 3;              // head group 0..3 (scores reduction)
    float zacc1 = 0.f, zacc2 = 0.f;  // heads g8, g8+4 at (lane&7)==0

    int my_r = tid >> 3;
    int my_q = tid & 7;

    if (ntiles > 0) {
        int m0 = min(TR, cnt);
        if (my_r < m0) {
            int row = __ldg(&g_sorted[base + my_r]);
            const float4* src = ((const float4*)x) + (size_t)row * 64 + my_q;
            float4* dst = ((float4*)(xs + (size_t)my_r * HIDDIM)) + my_q;
            #pragma unroll
            for (int kk = 0; kk < 8; kk++)
                cpa16(dst + 8 * kk, src + 8 * kk);
        }
    }
    cpa_commit();

    for (int t = 0; t < ntiles; t++) {
        int b = t & 1;
        int m = min(TR, cnt - t * TR);
        float* xsb = xs + (size_t)b * TR * HIDDIM;

        if (t + 1 < ntiles) {
            int m2 = min(TR, cnt - (t + 1) * TR);
            float* xsn = xs + (size_t)(b ^ 1) * TR * HIDDIM;
            if (my_r < m2) {
                int row = __ldg(&g_sorted[base + (t + 1) * TR + my_r]);
                const float4* src = ((const float4*)x) + (size_t)row * 64 + my_q;
                float4* dst = ((float4*)(xsn + (size_t)my_r * HIDDIM)) + my_q;
                #pragma unroll
                for (int kk = 0; kk < 8; kk++)
                    cpa16(dst + 8 * kk, src + 8 * kk);
            }
            cpa_commit();
            cpa_wait<1>();
        } else {
            cpa_wait<0>();
        }
        __syncthreads();

        // ---- scores: warp handles rows 4*warp .. 4*warp+3 ----
        {
            float2 s[4][4];
            #pragma unroll
            for (int rr = 0; rr < 4; rr++)
                #pragma unroll
                for (int p = 0; p < 4; p++) s[rr][p] = make_float2(0.f, 0.f);

            #pragma unroll
            for (int k = 0; k < 8; k++) {
                int j = lane + 32 * k;
                float2 q0 = QKs[0 * HIDDIM + j];
                float2 q1 = QKs[1 * HIDDIM + j];
                float2 q2 = QKs[2 * HIDDIM + j];
                float2 q3 = QKs[3 * HIDDIM + j];
                #pragma unroll
                for (int rr = 0; rr < 4; rr++) {
                    float xv = xsb[(warp * 4 + rr) * HIDDIM + j];
                    float2 xx = make_float2(xv, xv);
                    s[rr][0] = ffma2(xx, q0, s[rr][0]);
                    s[rr][1] = ffma2(xx, q1, s[rr][1]);
                    s[rr][2] = ffma2(xx, q2, s[rr][2]);
                    s[rr][3] = ffma2(xx, q3, s[rr][3]);
                }
            }
            #pragma unroll
            for (int rr = 0; rr < 4; rr++) {
                int r = warp * 4 + rr;
                float v[8] = {s[rr][0].x, s[rr][0].y, s[rr][1].x, s[rr][1].y,
                              s[rr][2].x, s[rr][2].y, s[rr][3].x, s[rr][3].y};
                #pragma unroll
                for (int h = 0; h < 8; h++) {
                    v[h] += __shfl_xor_sync(0xffffffffu, v[h], 16);
                    v[h] += __shfl_xor_sync(0xffffffffu, v[h], 8);
                }
                float w1 = (g8 == 0) ? v[0] : (g8 == 1) ? v[1] : (g8 == 2) ? v[2] : v[3];
                float w2 = (g8 == 0) ? v[4] : (g8 == 1) ? v[5] : (g8 == 2) ? v[6] : v[7];
                w1 += __shfl_xor_sync(0xffffffffu, w1, 1);
                w1 += __shfl_xor_sync(0xffffffffu, w1, 2);
                w1 += __shfl_xor_sync(0xffffffffu, w1, 4);
                w2 += __shfl_xor_sync(0xffffffffu, w2, 1);
                w2 += __shfl_xor_sync(0xffffffffu, w2, 2);
                w2 += __shfl_xor_sync(0xffffffffu, w2, 4);
                if ((lane & 7) == 0 && r < m) {
                    float e1 = __expf(w1 + bqs[g8]);
                    float e2 = __expf(w2 + bqs[g8 + 4]);
                    esf[r * 8 + g8]     = e1;
                    esf[r * 8 + g8 + 4] = e2;
                    zacc1 += e1;
                    zacc2 += e2;
                }
            }
        }
        __syncthreads();

        // ---- accumulate T: thread owns 4 cols, rows r == q (mod 4) ----
        for (int r = q; r < m; r += 4) {
            float4 xv = ((const float4*)(xsb + r * HIDDIM))[cg];
            float4 ea = ((const float4*)(esf + r * 8))[0];
            float4 eb = ((const float4*)(esf + r * 8))[1];
            float2 xlo = make_float2(xv.x, xv.y), xhi = make_float2(xv.z, xv.w);
            T[0][0] = ffma2(make_float2(ea.x, ea.x), xlo, T[0][0]);
            T[0][1] = ffma2(make_float2(ea.x, ea.x), xhi, T[0][1]);
            T[1][0] = ffma2(make_float2(ea.y, ea.y), xlo, T[1][0]);
            T[1][1] = ffma2(make_float2(ea.y, ea.y), xhi, T[1][1]);
            T[2][0] = ffma2(make_float2(ea.z, ea.z), xlo, T[2][0]);
            T[2][1] = ffma2(make_float2(ea.z, ea.z), xhi, T[2][1]);
            T[3][0] = ffma2(make_float2(ea.w, ea.w), xlo, T[3][0]);
            T[3][1] = ffma2(make_float2(ea.w, ea.w), xhi, T[3][1]);
            T[4][0] = ffma2(make_float2(eb.x, eb.x), xlo, T[4][0]);
            T[4][1] = ffma2(make_float2(eb.x, eb.x), xhi, T[4][1]);
            T[5][0] = ffma2(make_float2(eb.y, eb.y), xlo, T[5][0]);
            T[5][1] = ffma2(make_float2(eb.y, eb.y), xhi, T[5][1]);
            T[6][0] = ffma2(make_float2(eb.z, eb.z), xlo, T[6][0]);
            T[6][1] = ffma2(make_float2(eb.z, eb.z), xhi, T[6][1]);
            T[7][0] = ffma2(make_float2(eb.w, eb.w), xlo, T[7][0]);
            T[7][1] = ffma2(make_float2(eb.w, eb.w), xhi, T[7][1]);
        }
        __syncthreads();
    }

    // ---- epilogue: cross-quad reduction via xs (safe: all tile reads done) ----
    float* red = xs;   // 4 * 8 * 256 floats = 32 KB
    #pragma unroll
    for (int h = 0; h < 8; h++) {
        float2* dst = (float2*)(red + ((q * 8 + h) << 8) + cg * 4);
        dst[0] = T[h][0];
        dst[1] = T[h][1];
    }
    __syncthreads();
    float* Tp = g_T + (size_t)blockIdx.x * 8 * HIDDIM;
    #pragma unroll
    for (int h = 0; h < 8; h++) {
        float v = red[(0 * 8 + h) * 256 + tid] + red[(1 * 8 + h) * 256 + tid]
                + red[(2 * 8 + h) * 256 + tid] + red[(3 * 8 + h) * 256 + tid];
        Tp[h * HIDDIM + tid] = v;
    }

    if ((lane & 7) == 0) {
        zsh[warp * 8 + g8]     = zacc1;
        zsh[warp * 8 + g8 + 4] = zacc2;
    }
    __syncthreads();
    if (tid < 8) {
        float z = 0.f;
        #pragma unroll
        for (int w = 0; w < 8; w++) z += zsh[w * 8 + tid];
        g_z[blockIdx.x * 8 + tid] = z;
    }
}

// ---------------- gemm: pooled (Wv) -> outc (Wo) ----------------
__global__ void __launch_bounds__(256) k_gemm(
    const float* __restrict__ Wv, const float* __restrict__ bv,
    const float* __restrict__ Wo, const float* __restrict__ bo) {
    __shared__ float Ws[256 * 33];
    __shared__ float TsPp[2112];
    __shared__ float sinvz[64];
    __shared__ float sinvc[8];

    int tid = threadIdx.x;
    int c0 = blockIdx.x * 8;
    int h = tid >> 5;

    if (tid < 64) {
        int cc = tid >> 3, hh = tid & 7;
        float z = 0.f;
        #pragma unroll
        for (int p = 0; p < SPLIT; p++)
            z += g_z[(c0 + cc) * (8 * SPLIT) + p * 8 + hh];
        sinvz[tid] = (z > 0.f) ? 1.f / z : 0.f;
    }
    if (tid < 8) {
        int cnt = g_offsets[c0 + tid + 1] - g_offsets[c0 + tid];
        sinvc[tid] = (cnt > 0) ? 1.f / (float)cnt : 0.f;
    }

    float acc[8];
    #pragma unroll
    for (int cc = 0; cc < 8; cc++) acc[cc] = 0.f;

    for (int kt = 0; kt < HIDDIM; kt += 32) {
        __syncthreads();
        for (int i = tid; i < 8192; i += 256) {
            int hd = i >> 5, kk = i & 31;
            Ws[hd * 33 + kk] = Wv[hd * HIDDIM + kt + kk];
        }
        for (int i = tid; i < 2048; i += 256) {
            int cc = i >> 8, hh = (i >> 5) & 7, kk = i & 31;
            size_t b0 = ((size_t)(c0 + cc) * SPLIT) * 2048 + hh * 256 + kt + kk;
            float tv = 0.f;
            #pragma unroll
            for (int p = 0; p < SPLIT; p++) tv += g_T[b0 + (size_t)p * 2048];
            TsPp[(cc * 8 + hh) * 33 + kk] = tv * sinvz[cc * 8 + hh];
        }
        __syncthreads();
        for (int kk = 0; kk < 32; kk++) {
            float w = Ws[tid * 33 + kk];
            #pragma unroll
            for (int cc = 0; cc < 8; cc++) acc[cc] += TsPp[(cc * 8 + h) * 33 + kk] * w;
        }
    }
    __syncthreads();
    {
        float bvv = bv[tid];
        #pragma unroll
        for (int cc = 0; cc < 8; cc++)
            TsPp[cc * 256 + tid] = (acc[cc] + bvv) * sinvc[cc];  // pooled rows
    }
    __syncthreads();

    float acc2[8];
    #pragma unroll
    for (int cc = 0; cc < 8; cc++) acc2[cc] = 0.f;

    for (int kt = 0; kt < HIDDIM; kt += 32) {
        __syncthreads();
        for (int i = tid; i < 8192; i += 256) {
            int hd = i >> 5, kk = i & 31;
            Ws[hd * 33 + kk] = Wo[hd * HIDDIM + kt + kk];
        }
        __syncthreads();
        for (int kk = 0; kk < 32; kk++) {
            float w = Ws[tid * 33 + kk];
            #pragma unroll
            for (int cc = 0; cc < 8; cc++) acc2[cc] += TsPp[cc * 256 + kt + kk] * w;
        }
    }
    {
        float bov = bo[tid];
        #pragma unroll
        for (int cc = 0; cc < 8; cc++)
            g_outc[(size_t)(c0 + cc) * HIDDIM + tid] = acc2[cc] + bov;
    }
}

// ---------------- out[n,:] = outc[ca[n],:]  (streaming stores) ----------------
__global__ void k_bcast(const int* __restrict__ ca, float* __restrict__ out) {
    int r = blockIdx.x * 4 + (threadIdx.x >> 6);
    int t64 = threadIdx.x & 63;
    int c = __ldg(&ca[r]);
    float4 v = __ldg(((const float4*)g_outc) + (size_t)c * 64 + t64);
    __stcs(((float4*)out) + (size_t)r * 64 + t64, v);
}

// ---------------- launch ----------------
extern "C" void kernel_launch(void* const* d_in, const int* in_sizes, int n_in,
                              void* d_out, int out_size) {
    const float* x  = (const float*)d_in[0];
    const int*   ca = (const int*)d_in[1];
    // d_in[2] = batch (unused)
    const float* Wk = (const float*)d_in[3];
    const float* bk = (const float*)d_in[4];
    const float* Wv = (const float*)d_in[5];
    const float* bv = (const float*)d_in[6];
    const float* Wo = (const float*)d_in[7];
    const float* bo = (const float*)d_in[8];
    const float* pq = (const float*)d_in[9];
    float* out = (float*)d_out;

    cudaFuncSetAttribute(k_main, cudaFuncAttributeMaxDynamicSharedMemorySize,
                         SMEM_MAIN);

    k_prep_hist<<<NB + 8, 256>>>(Wk, bk, pq, ca);
    k_scan2    <<<1, 1024>>>();
    k_scatter2 <<<NB, 256>>>(ca);
    k_main     <<<SPLIT * NC, 256, SMEM_MAIN>>>(x);
    k_gemm     <<<NC / 8, 256>>>(Wv, bv, Wo, bo);
    k_bcast    <<<N_NODES / 4, 256>>>(ca, out);
}